// round 9
// baseline (speedup 1.0000x reference)
#include <cuda_runtime.h>
#include <math.h>

#define BB 8
#define TT 512
#define DD 1024
#define SS 2048
#define HH 4
#define D2 2048

// ---------------- device scratch (no allocations allowed) ----------------
__device__ float g_h[BB*TT*DD];        // backbone activations [B,T,D]
__device__ float g_tmp[BB*TT*D2];      // backbone intermediate [B*T, 2D]
__device__ float g_y[BB*TT*DD];        // backbone y [B*T, D]
__device__ float g_K[SS*DD];           // mutable memory keys
__device__ float g_V[SS*DD];           // mutable memory values (stored units; actual = c * stored)
__device__ float g_fuseWT[DD*D2];      // fuse_W transposed: [D][2D]
__device__ float g_scores[BB*HH*SS];
__device__ float g_sw[BB*SS];
__device__ float g_vt[BB*DD];
__device__ float g_fusedpre[BB*DD];
__device__ float g_oldV[BB*DD];        // snapshot of V rows (stored units) at this step's slots
__device__ int   g_slot[BB];
__device__ float g_lr[BB];
__device__ unsigned char g_anyt[TT];   // precomputed per-step write-any flag
__device__ unsigned g_barcnt;
__device__ volatile unsigned g_bargen;

// ---------------- helpers ----------------
__device__ __forceinline__ float gelu_f(float x){
    float x3 = x*x*x;
    return 0.5f*x*(1.f + tanhf(0.7978845608028654f*(x + 0.044715f*x3)));
}

// block-wide sum for 256-thread blocks; a needs >= 9 floats
__device__ __forceinline__ float blk_sum256(float x, float* a, int tid){
#pragma unroll
    for (int o=16;o;o>>=1) x += __shfl_xor_sync(0xffffffffu, x, o);
    if ((tid&31)==0) a[tid>>5] = x;
    __syncthreads();
    if (tid==0){
        float t=0;
#pragma unroll
        for (int w=0;w<8;w++) t += a[w];
        a[8]=t;
    }
    __syncthreads();
    return a[8];
}

// hand-rolled grid barrier (all CTAs resident: 1 CTA/SM enforced by 120KB smem)
// 1-hop: last arriver flips gen directly; waiters pure-spin on the L2 line.
__device__ __forceinline__ void gsync(unsigned nb){
    __syncthreads();
    if (threadIdx.x==0){
        __threadfence();
        unsigned gen = g_bargen;
        if (atomicAdd(&g_barcnt, 1u) == nb-1u){
            g_barcnt = 0;
            __threadfence();
            g_bargen = gen+1u;
        } else {
            while (g_bargen == gen) { }
            __threadfence();
        }
    }
    __syncthreads();
}

// ---------------- backbone GEMM: C = act(A[M,K] @ B[K,N] + bias) ----------------
__global__ __launch_bounds__(256) void gemm128(const float* __restrict__ A,
                                               const float* __restrict__ B,
                                               const float* __restrict__ bias,
                                               float* __restrict__ C,
                                               int M, int N, int K, int act)
{
    __shared__ float As[16][128];
    __shared__ float Bs[16][128];
    const int tid = threadIdx.x;
    const int m0 = blockIdx.y*128, n0 = blockIdx.x*128;
    const int tr = tid>>4, tc = tid&15;
    float acc[8][8];
#pragma unroll
    for (int i=0;i<8;i++)
#pragma unroll
        for (int j=0;j<8;j++) acc[i][j]=0.f;

    for (int k0=0;k0<K;k0+=16){
#pragma unroll
        for (int it=0; it<2; it++){
            int id = tid + it*256;
            int r = id>>2, c4 = id&3;
            float4 v = *(const float4*)(A + (size_t)(m0+r)*K + k0 + c4*4);
            As[c4*4+0][r]=v.x; As[c4*4+1][r]=v.y; As[c4*4+2][r]=v.z; As[c4*4+3][r]=v.w;
        }
#pragma unroll
        for (int it=0; it<2; it++){
            int id = tid + it*256;
            int r = id>>5, c4 = id&31;
            *(float4*)(&Bs[r][c4*4]) = *(const float4*)(B + (size_t)(k0+r)*N + n0 + c4*4);
        }
        __syncthreads();
#pragma unroll
        for (int k=0;k<16;k++){
            float a[8], br[8];
            *(float4*)(a)   = *(float4*)(&As[k][tr*8]);
            *(float4*)(a+4) = *(float4*)(&As[k][tr*8+4]);
            *(float4*)(br)   = *(float4*)(&Bs[k][tc*8]);
            *(float4*)(br+4) = *(float4*)(&Bs[k][tc*8+4]);
#pragma unroll
            for (int i=0;i<8;i++)
#pragma unroll
                for (int j=0;j<8;j++) acc[i][j] += a[i]*br[j];
        }
        __syncthreads();
    }
#pragma unroll
    for (int i=0;i<8;i++){
        int row = m0 + tr*8 + i;
#pragma unroll
        for (int j=0;j<8;j++){
            float v = acc[i][j] + bias[n0 + tc*8 + j];
            if (act) v = gelu_f(v);
            C[(size_t)row*N + n0 + tc*8 + j] = v;
        }
    }
}

// ---------------- backbone LN + residual: h += LN(y)*g+b ----------------
__global__ __launch_bounds__(256) void ln_res(float* __restrict__ h, const float* __restrict__ y,
                                              const float* __restrict__ g, const float* __restrict__ bb)
{
    __shared__ float a[16];
    int row = blockIdx.x, tid = threadIdx.x;
    const float* yr = y + (size_t)row*DD;
    float v[4];
#pragma unroll
    for (int k=0;k<4;k++) v[k] = yr[tid + k*256];
    float s = v[0]+v[1]+v[2]+v[3];
    float tot = blk_sum256(s, a, tid);
    float mean = tot * (1.f/1024.f);
    float s2=0.f;
#pragma unroll
    for (int k=0;k<4;k++){ float d=v[k]-mean; s2 += d*d; }
    float tot2 = blk_sum256(s2, a, tid);
    float rs = rsqrtf(tot2*(1.f/1024.f) + 1e-5f);
    float* hr = h + (size_t)row*DD;
#pragma unroll
    for (int k=0;k<4;k++){
        int j = tid + k*256;
        hr[j] += (v[k]-mean)*rs*g[j] + bb[j];
    }
}

// ---------------- init: transpose fuse_W, reset barrier, precompute anyt ----------------
__global__ void init_kernel(const float* __restrict__ W, const int* __restrict__ mask)
{
    __shared__ float tile[32][33];
    int i0 = blockIdx.y*32;   // over 2D=2048
    int j0 = blockIdx.x*32;   // over D=1024
    int tx = threadIdx.x, ty = threadIdx.y;
#pragma unroll
    for (int r=0;r<4;r++)
        tile[ty+8*r][tx] = W[(size_t)(i0+ty+8*r)*DD + j0+tx];
    __syncthreads();
#pragma unroll
    for (int r=0;r<4;r++)
        g_fuseWT[(size_t)(j0+ty+8*r)*D2 + i0+tx] = tile[tx][ty+8*r];
    if (blockIdx.x==0 && blockIdx.y==0 && tx==0 && ty==0){ g_barcnt=0; g_bargen=0; }
    if (blockIdx.x==0 && blockIdx.y==1){
        int id = ty*32 + tx;          // 0..255
        for (int t=id; t<TT; t+=256){
            int a = 0;
#pragma unroll
            for (int b=0;b<BB;b++) a |= (mask[b*TT+t] != 0);
            g_anyt[t] = (unsigned char)a;
        }
    }
}

// ---------------- deferred Phase D: LN + out + V scatter for step tprev ----------------
// executed by blocks 0..7 (block b handles batch b); invc = 1/scale_after_decay(tprev)
__device__ __forceinline__ void phaseD(int b, int tprev, float invc,
                                       const float* __restrict__ mln_g,
                                       const float* __restrict__ mln_b,
                                       float* __restrict__ out,
                                       float* auxv, int tid)
{
    float v[4];
#pragma unroll
    for (int k=0;k<4;k++) v[k] = g_fusedpre[b*DD + tid + k*256];
    float s = v[0]+v[1]+v[2]+v[3];
    float tot = blk_sum256(s, auxv, tid);
    float mean = tot*(1.f/1024.f);
    float s2=0.f;
#pragma unroll
    for (int k=0;k<4;k++){ float d=v[k]-mean; s2+=d*d; }
    float tot2 = blk_sum256(s2, auxv, tid);
    float rs = rsqrtf(tot2*(1.f/1024.f) + 1e-5f);
    int sl = g_slot[b]; float lr = g_lr[b];
#pragma unroll
    for (int k=0;k<4;k++){
        int j = tid + k*256;
        float f = (v[k]-mean)*rs*mln_g[j] + mln_b[j];
        out[((size_t)b*TT + tprev)*DD + j] = f;
        float dv = lr*(f*invc - g_oldV[b*DD + j]);
        atomicAdd(&g_V[(size_t)sl*DD + j], dv);
    }
    __syncthreads();
}

// ---------------- persistent scan kernel (3 grid barriers per step) ----------------
// mask is int32 (harness widens bool; nonzero == True)
__global__ __launch_bounds__(256,1) void scan_kernel(
    const int* __restrict__ mask,
    const float* __restrict__ fuse_b,
    const float* __restrict__ mln_g,
    const float* __restrict__ mln_b,
    float* __restrict__ out,
    int nblocks)
{
    extern __shared__ float sm[];
    float* cat  = sm;              // [8][2048]: first 1024 = h_t, last 1024 = v_t
    float* auxv = sm + BB*D2;      // 128 floats
    int*   auxi = (int*)(auxv + 128);

    const int tid  = threadIdx.x;
    const int lane = tid & 31;
    const int wib  = tid >> 5;     // 0..7
    const int bid  = blockIdx.x;
    const int gw   = bid*8 + wib;
    const int nw   = nblocks*8;
    const int nA   = nblocks - 8;  // CTAs doing Phase A (blocks 8..nblocks-1)
    // cr = V scale entering step t (includes decay of all steps < t); actual_V = cr*stored_V
    double cr = 1.0;

    for (int t=0; t<TT; t++){
        float crf = (float)cr;
        float invcr = 1.f/crf;

        // ---- stage h_t into smem (q half of cat) ----
        for (int idx=tid; idx < BB*DD/4; idx += 256){
            int b = idx>>8, j4 = idx&255;
            *(float4*)(cat + b*D2 + j4*4) =
                *(const float4*)(g_h + ((size_t)(b*TT+t))*DD + j4*4);
        }
        __syncthreads();

        if (bid < 8){
            // ---- blocks 0-7: ONLY deferred Phase D for step t-1 (no Phase A share) ----
            if (t>0)
                phaseD(bid, t-1, invcr, mln_g, mln_b, out, auxv, tid);
        } else {
            // ---- Phase A on blocks 8..: balanced contiguous row chunks ----
            // lane mapping: 8-lane group g=lane>>3 owns head g; 5-shuffle reduction.
            int active = bid - 8;
            int r0 = (active    * SS) / nA;
            int r1 = ((active+1)* SS) / nA;
            const int hg = lane >> 3, su = lane & 7;
            const int fbase = hg*64 + su;       // float4 index within the 256-float4 row
            for (int s = r0 + wib; s < r1; s += 8){
                const float4* Kr = (const float4*)(g_K + (size_t)s*DD);
                float4 kreg[8];
#pragma unroll
                for (int j=0;j<8;j++) kreg[j] = Kr[fbase + 8*j];
                for (int b=0;b<BB;b++){
                    const float4* qb = (const float4*)(cat + b*D2);
                    float p = 0.f;
#pragma unroll
                    for (int j=0;j<8;j++){
                        float4 q = qb[fbase + 8*j];
                        p += kreg[j].x*q.x + kreg[j].y*q.y + kreg[j].z*q.z + kreg[j].w*q.w;
                    }
                    // head sum within 8-lane group
                    p += __shfl_xor_sync(0xffffffffu, p, 1);
                    p += __shfl_xor_sync(0xffffffffu, p, 2);
                    p += __shfl_xor_sync(0xffffffffu, p, 4);
                    // full-row sum across the 4 groups
                    float tsum = p + __shfl_xor_sync(0xffffffffu, p, 8);
                    tsum += __shfl_xor_sync(0xffffffffu, tsum, 16);
                    if (su == 0){
                        g_scores[(b*HH+hg)*SS + s] = p * 0.0625f;
                        if (hg == 0) g_sw[b*SS + s] = tsum * 0.03125f;
                    }
                }
            }
        }
        gsync(nblocks);   // scores/sw ready AND D(t-1)'s V writes visible

        // ---- Phase B: top-8 + softmax + V gather (32 blocks) || sw reduce (8 blocks) ----
        if (bid < 32){
            int b = bid>>2, h = bid&3;
            const float* sc = g_scores + (b*HH+h)*SS;
            // warp-local top-8: warps 0..7 each own 256 contiguous scores
            {
                float vals[8];
                const int base = wib*256 + lane;
#pragma unroll
                for (int i=0;i<8;i++) vals[i] = sc[base + i*32];
                for (int k=0;k<8;k++){
                    float bv=-1e30f; int bi=0x7fffffff;
#pragma unroll
                    for (int i=0;i<8;i++){
                        int idx = base + i*32;
                        float v = vals[i];
                        if (v>bv || (v==bv && idx<bi)){ bv=v; bi=idx; }
                    }
#pragma unroll
                    for (int o=16;o;o>>=1){
                        float ov=__shfl_xor_sync(0xffffffffu,bv,o);
                        int   oi=__shfl_xor_sync(0xffffffffu,bi,o);
                        if (ov>bv || (ov==bv && oi<bi)){ bv=ov; bi=oi; }
                    }
                    if (lane==k){ auxv[wib*8+k]=bv; auxi[wib*8+k]=bi; }
                    int local = bi - wib*256;
                    if ((local&31)==lane) vals[local>>5] = -1e30f;
                }
            }
            __syncthreads();
            // warp 0 merges 64 candidates -> global top-8, softmax weights
            if (wib==0){
                float c0 = auxv[lane],    c1 = auxv[lane+32];
                int   i0 = auxi[lane],    i1 = auxi[lane+32];
                float topv[8]; int topi[8];
#pragma unroll
                for (int k=0;k<8;k++){
                    float bv; int bi;
                    if (c0>c1 || (c0==c1 && i0<i1)){ bv=c0; bi=i0; } else { bv=c1; bi=i1; }
#pragma unroll
                    for (int o=16;o;o>>=1){
                        float ov=__shfl_xor_sync(0xffffffffu,bv,o);
                        int   oi=__shfl_xor_sync(0xffffffffu,bi,o);
                        if (ov>bv || (ov==bv && oi<bi)){ bv=ov; bi=oi; }
                    }
                    topv[k]=bv; topi[k]=bi;
                    if (i0==bi){ c0=-1e30f; i0=0x7fffffff; }
                    if (i1==bi){ c1=-1e30f; i1=0x7fffffff; }
                }
                float m0 = topv[0], sum=0.f, w8[8];
#pragma unroll
                for (int k=0;k<8;k++){ w8[k]=expf(topv[k]-m0); sum += w8[k]; }
                float inv = 1.f/sum;
                if (lane<8){ auxv[64+lane] = w8[lane]*inv; auxi[64+lane] = topi[lane]; }
            }
            __syncthreads();
            // gather V (all 256 threads; Dh=256)
            {
                float acc = 0.f;
#pragma unroll
                for (int k=0;k<8;k++)
                    acc += auxv[64+k] * g_V[(size_t)auxi[64+k]*DD + h*256 + tid];
                g_vt[b*DD + h*256 + tid] = acc * crf;
            }
        } else if (bid < 40){
            int b = bid - 32;
            const float* sw = g_sw + b*SS;
            float bv=-1e30f; int bi=0x7fffffff;
            for (int s=tid;s<SS;s+=256){
                float v = sw[s];
                if (v>bv || (v==bv && s<bi)){ bv=v; bi=s; }
            }
#pragma unroll
            for (int o=16;o;o>>=1){
                float ov = __shfl_xor_sync(0xffffffffu,bv,o);
                int   oi = __shfl_xor_sync(0xffffffffu,bi,o);
                if (ov>bv || (ov==bv && oi<bi)){ bv=ov; bi=oi; }
            }
            if (lane==0){ auxv[wib]=bv; auxi[wib]=bi; }
            __syncthreads();
            if (tid==0){
                float fv=auxv[0]; int fi=auxi[0];
#pragma unroll
                for (int w=1;w<8;w++){
                    float ov=auxv[w]; int oi=auxi[w];
                    if (ov>fv || (ov==fv && oi<fi)){ fv=ov; fi=oi; }
                }
                auxv[8]=fv; auxi[8]=fi;
            }
            __syncthreads();
            float M = auxv[8];
            float ps=0.f;
            for (int s=tid;s<SS;s+=256) ps += expf(sw[s]-M);
#pragma unroll
            for (int o=16;o;o>>=1) ps += __shfl_xor_sync(0xffffffffu,ps,o);
            if (lane==0) auxv[16+wib]=ps;
            __syncthreads();
            if (tid==0){
                float sum=0.f;
#pragma unroll
                for (int w=0;w<8;w++) sum += auxv[16+w];
                float sur = 1.f - 1.f/sum;
                float gate = (mask[b*TT+t] != 0) ? 1.f : 0.f;
                g_lr[b]  = (sur > 0.6f ? 1.0f : 0.1f) * gate;
                g_slot[b] = auxi[8];
            }
        }
        gsync(nblocks);

        // ---- Phase C: fusion GEMV (1024 col-tasks) + K update + V snapshot ----
        for (int idx=tid; idx < BB*DD/4; idx += 256){
            int b = idx>>8, j4 = idx&255;
            *(float4*)(cat + b*D2 + 1024 + j4*4) = *(const float4*)(g_vt + b*DD + j4*4);
        }
        __syncthreads();
        for (int task=gw; task<1088; task+=nw){
            if (task < 1024){
                int j = task;
                const float4* Wr = (const float4*)(g_fuseWT + (size_t)j*D2);
                float4 wreg[16];
#pragma unroll
                for (int c=0;c<16;c++) wreg[c] = Wr[lane + 32*c];
                float res[BB];
                for (int b=0;b<BB;b++){
                    float acc=0.f;
#pragma unroll
                    for (int c=0;c<16;c++){
                        float4 x = *(const float4*)(cat + b*D2 + 4*(lane + 32*c));
                        acc += wreg[c].x*x.x + wreg[c].y*x.y + wreg[c].z*x.z + wreg[c].w*x.w;
                    }
#pragma unroll
                    for (int o=16;o;o>>=1) acc += __shfl_xor_sync(0xffffffffu,acc,o);
                    res[b]=acc;
                }
                if (lane==0){
                    float fb = fuse_b[j];
#pragma unroll
                    for (int b=0;b<BB;b++)
                        g_fusedpre[b*DD + j] = res[b] + fb + cat[b*D2 + j]; // + h_t residual
                }
            } else if (task < 1056){
                int col = (task-1024)*32 + lane;
                int   sl[BB]; float lrv[BB], oldk[BB];
#pragma unroll
                for (int b=0;b<BB;b++){ sl[b]=g_slot[b]; lrv[b]=g_lr[b]; }
#pragma unroll
                for (int b=0;b<BB;b++) oldk[b] = g_K[(size_t)sl[b]*DD + col];
#pragma unroll
                for (int b=0;b<BB;b++)
                    g_K[(size_t)sl[b]*DD + col] += lrv[b]*(cat[b*D2 + col] - oldk[b]);
            } else {
                int col = (task-1056)*32 + lane;
#pragma unroll
                for (int b=0;b<BB;b++)
                    g_oldV[b*DD + col] = g_V[(size_t)g_slot[b]*DD + col];
            }
        }
        gsync(nblocks);   // fusedpre/oldV/K ready for D(t) and A(t+1)

        // apply this step's decay to the carried scale (precomputed anyt flag)
        if (g_anyt[t]) cr *= 0.9995;
    }

    // final deferred Phase D for t = TT-1
    if (bid < BB){
        float invc = 1.f/(float)cr;
        phaseD(bid, TT-1, invc, mln_g, mln_b, out, auxv, tid);
    }
}

// ---------------- launch ----------------
extern "C" void kernel_launch(void* const* d_in, const int* in_sizes, int n_in,
                              void* d_out, int out_size)
{
    const float* x      = (const float*)d_in[0];
    const int*   mask   = (const int*)d_in[1];     // bool widened to int32 by harness
    const float* W1     = (const float*)d_in[2];
    const float* b1     = (const float*)d_in[3];
    const float* W2     = (const float*)d_in[4];
    const float* b2     = (const float*)d_in[5];
    const float* ln_g   = (const float*)d_in[6];
    const float* ln_b   = (const float*)d_in[7];
    const float* fuse_W = (const float*)d_in[8];
    const float* fuse_b = (const float*)d_in[9];
    const float* mln_g  = (const float*)d_in[10];
    const float* mln_b  = (const float*)d_in[11];
    const float* mem_K  = (const float*)d_in[12];
    const float* mem_V  = (const float*)d_in[13];
    float* out = (float*)d_out;

    void *p_h, *p_tmp, *p_y, *p_K, *p_V;
    cudaGetSymbolAddress(&p_h,   g_h);
    cudaGetSymbolAddress(&p_tmp, g_tmp);
    cudaGetSymbolAddress(&p_y,   g_y);
    cudaGetSymbolAddress(&p_K,   g_K);
    cudaGetSymbolAddress(&p_V,   g_V);

    cudaMemcpyAsync(p_h, x,     (size_t)BB*TT*DD*sizeof(float), cudaMemcpyDeviceToDevice, 0);
    cudaMemcpyAsync(p_K, mem_K, (size_t)SS*DD*sizeof(float),    cudaMemcpyDeviceToDevice, 0);
    cudaMemcpyAsync(p_V, mem_V, (size_t)SS*DD*sizeof(float),    cudaMemcpyDeviceToDevice, 0);

    init_kernel<<<dim3(DD/32, D2/32), dim3(32,8), 0, 0>>>(fuse_W, mask);

    for (int i=0;i<2;i++){
        gemm128<<<dim3(D2/128, (BB*TT)/128), 256, 0, 0>>>(
            (const float*)p_h, W1 + (size_t)i*DD*D2, b1 + (size_t)i*D2,
            (float*)p_tmp, BB*TT, D2, DD, 1);
        gemm128<<<dim3(DD/128, (BB*TT)/128), 256, 0, 0>>>(
            (const float*)p_tmp, W2 + (size_t)i*D2*DD, b2 + (size_t)i*DD,
            (float*)p_y, BB*TT, DD, D2, 0);
        ln_res<<<BB*TT, 256, 0, 0>>>((float*)p_h, (const float*)p_y,
                                     ln_g + (size_t)i*DD, ln_b + (size_t)i*DD);
    }

    int nsm = 148;
    cudaDeviceGetAttribute(&nsm, cudaDevAttrMultiProcessorCount, 0);
    size_t smem = 120*1024;  // forces 1 CTA/SM -> all CTAs co-resident for the grid barrier
    cudaFuncSetAttribute(scan_kernel, cudaFuncAttributeMaxDynamicSharedMemorySize, (int)smem);
    scan_kernel<<<nsm, 256, smem, 0>>>(mask, fuse_b, mln_g, mln_b, out, nsm);
}

// round 17
// speedup vs baseline: 1.0375x; 1.0375x over previous
#include <cuda_runtime.h>
#include <math.h>

#define BB 8
#define TT 512
#define DD 1024
#define SS 2048
#define HH 4
#define D2 2048

// ---------------- device scratch (no allocations allowed) ----------------
__device__ float g_h[BB*TT*DD];        // backbone activations [B,T,D]
__device__ float g_tmp[BB*TT*D2];      // backbone intermediate [B*T, 2D]
__device__ float g_y[BB*TT*DD];        // backbone y [B*T, D]
__device__ float g_K[SS*DD];           // mutable memory keys
__device__ float g_V[SS*DD];           // mutable memory values (stored units; actual = c * stored)
__device__ float g_fuseWT[DD*D2];      // fuse_W transposed: [D][2D]
__device__ float g_scores[BB*HH*SS];
__device__ float g_sw[BB*SS];
__device__ float g_vt[BB*DD];
__device__ float g_fusedpre[BB*DD];
__device__ float g_oldV[BB*DD];        // snapshot of V rows (stored units) at this step's slots
__device__ int   g_slot[BB];
__device__ float g_lr[BB];
__device__ unsigned char g_anyt[TT];   // precomputed per-step write-any flag
__device__ unsigned g_barcnt;
__device__ volatile unsigned g_bargen;

// ---------------- helpers ----------------
__device__ __forceinline__ float gelu_f(float x){
    float x3 = x*x*x;
    return 0.5f*x*(1.f + tanhf(0.7978845608028654f*(x + 0.044715f*x3)));
}

// block-wide sum for 256-thread blocks; a needs >= 9 floats
__device__ __forceinline__ float blk_sum256(float x, float* a, int tid){
#pragma unroll
    for (int o=16;o;o>>=1) x += __shfl_xor_sync(0xffffffffu, x, o);
    if ((tid&31)==0) a[tid>>5] = x;
    __syncthreads();
    if (tid==0){
        float t=0;
#pragma unroll
        for (int w=0;w<8;w++) t += a[w];
        a[8]=t;
    }
    __syncthreads();
    return a[8];
}

// hand-rolled grid barrier (all CTAs resident: 1 CTA/SM enforced by 120KB smem)
// MEASURED-GOOD R8 form: nanosleep backoff keeps the release line uncontended.
__device__ __forceinline__ void gsync(unsigned nb){
    __syncthreads();
    if (threadIdx.x==0){
        __threadfence();
        unsigned gen = g_bargen;
        if (atomicAdd(&g_barcnt, 1u) == nb-1u){
            g_barcnt = 0;
            __threadfence();
            g_bargen = gen+1u;
        } else {
            while (g_bargen == gen) __nanosleep(64);
            __threadfence();
        }
    }
    __syncthreads();
}

// ---------------- backbone GEMM: C = act(A[M,K] @ B[K,N] + bias) ----------------
__global__ __launch_bounds__(256) void gemm128(const float* __restrict__ A,
                                               const float* __restrict__ B,
                                               const float* __restrict__ bias,
                                               float* __restrict__ C,
                                               int M, int N, int K, int act)
{
    __shared__ float As[16][128];
    __shared__ float Bs[16][128];
    const int tid = threadIdx.x;
    const int m0 = blockIdx.y*128, n0 = blockIdx.x*128;
    const int tr = tid>>4, tc = tid&15;
    float acc[8][8];
#pragma unroll
    for (int i=0;i<8;i++)
#pragma unroll
        for (int j=0;j<8;j++) acc[i][j]=0.f;

    for (int k0=0;k0<K;k0+=16){
#pragma unroll
        for (int it=0; it<2; it++){
            int id = tid + it*256;
            int r = id>>2, c4 = id&3;
            float4 v = *(const float4*)(A + (size_t)(m0+r)*K + k0 + c4*4);
            As[c4*4+0][r]=v.x; As[c4*4+1][r]=v.y; As[c4*4+2][r]=v.z; As[c4*4+3][r]=v.w;
        }
#pragma unroll
        for (int it=0; it<2; it++){
            int id = tid + it*256;
            int r = id>>5, c4 = id&31;
            *(float4*)(&Bs[r][c4*4]) = *(const float4*)(B + (size_t)(k0+r)*N + n0 + c4*4);
        }
        __syncthreads();
#pragma unroll
        for (int k=0;k<16;k++){
            float a[8], br[8];
            *(float4*)(a)   = *(float4*)(&As[k][tr*8]);
            *(float4*)(a+4) = *(float4*)(&As[k][tr*8+4]);
            *(float4*)(br)   = *(float4*)(&Bs[k][tc*8]);
            *(float4*)(br+4) = *(float4*)(&Bs[k][tc*8+4]);
#pragma unroll
            for (int i=0;i<8;i++)
#pragma unroll
                for (int j=0;j<8;j++) acc[i][j] += a[i]*br[j];
        }
        __syncthreads();
    }
#pragma unroll
    for (int i=0;i<8;i++){
        int row = m0 + tr*8 + i;
#pragma unroll
        for (int j=0;j<8;j++){
            float v = acc[i][j] + bias[n0 + tc*8 + j];
            if (act) v = gelu_f(v);
            C[(size_t)row*N + n0 + tc*8 + j] = v;
        }
    }
}

// ---------------- backbone LN + residual: h += LN(y)*g+b ----------------
__global__ __launch_bounds__(256) void ln_res(float* __restrict__ h, const float* __restrict__ y,
                                              const float* __restrict__ g, const float* __restrict__ bb)
{
    __shared__ float a[16];
    int row = blockIdx.x, tid = threadIdx.x;
    const float* yr = y + (size_t)row*DD;
    float v[4];
#pragma unroll
    for (int k=0;k<4;k++) v[k] = yr[tid + k*256];
    float s = v[0]+v[1]+v[2]+v[3];
    float tot = blk_sum256(s, a, tid);
    float mean = tot * (1.f/1024.f);
    float s2=0.f;
#pragma unroll
    for (int k=0;k<4;k++){ float d=v[k]-mean; s2 += d*d; }
    float tot2 = blk_sum256(s2, a, tid);
    float rs = rsqrtf(tot2*(1.f/1024.f) + 1e-5f);
    float* hr = h + (size_t)row*DD;
#pragma unroll
    for (int k=0;k<4;k++){
        int j = tid + k*256;
        hr[j] += (v[k]-mean)*rs*g[j] + bb[j];
    }
}

// ---------------- init: transpose fuse_W, reset barrier, precompute anyt ----------------
__global__ void init_kernel(const float* __restrict__ W, const int* __restrict__ mask)
{
    __shared__ float tile[32][33];
    int i0 = blockIdx.y*32;   // over 2D=2048
    int j0 = blockIdx.x*32;   // over D=1024
    int tx = threadIdx.x, ty = threadIdx.y;
#pragma unroll
    for (int r=0;r<4;r++)
        tile[ty+8*r][tx] = W[(size_t)(i0+ty+8*r)*DD + j0+tx];
    __syncthreads();
#pragma unroll
    for (int r=0;r<4;r++)
        g_fuseWT[(size_t)(j0+ty+8*r)*D2 + i0+tx] = tile[tx][ty+8*r];
    if (blockIdx.x==0 && blockIdx.y==0 && tx==0 && ty==0){ g_barcnt=0; g_bargen=0; }
    if (blockIdx.x==0 && blockIdx.y==1){
        int id = ty*32 + tx;          // 0..255
        for (int t=id; t<TT; t+=256){
            int a = 0;
#pragma unroll
            for (int b=0;b<BB;b++) a |= (mask[b*TT+t] != 0);
            g_anyt[t] = (unsigned char)a;
        }
    }
}

// ---------------- deferred Phase D: LN + out + V scatter for step tprev ----------------
// executed by blocks 0..7 (block b handles batch b); invc = 1/scale_after_decay(tprev)
__device__ __forceinline__ void phaseD(int b, int tprev, float invc,
                                       const float* __restrict__ mln_g,
                                       const float* __restrict__ mln_b,
                                       float* __restrict__ out,
                                       float* auxv, int tid)
{
    float v[4];
#pragma unroll
    for (int k=0;k<4;k++) v[k] = g_fusedpre[b*DD + tid + k*256];
    float s = v[0]+v[1]+v[2]+v[3];
    float tot = blk_sum256(s, auxv, tid);
    float mean = tot*(1.f/1024.f);
    float s2=0.f;
#pragma unroll
    for (int k=0;k<4;k++){ float d=v[k]-mean; s2+=d*d; }
    float tot2 = blk_sum256(s2, auxv, tid);
    float rs = rsqrtf(tot2*(1.f/1024.f) + 1e-5f);
    int sl = g_slot[b]; float lr = g_lr[b];
#pragma unroll
    for (int k=0;k<4;k++){
        int j = tid + k*256;
        float f = (v[k]-mean)*rs*mln_g[j] + mln_b[j];
        out[((size_t)b*TT + tprev)*DD + j] = f;
        float dv = lr*(f*invc - g_oldV[b*DD + j]);
        atomicAdd(&g_V[(size_t)sl*DD + j], dv);
    }
    __syncthreads();
}

// ---------------- persistent scan kernel (3 grid barriers per step) ----------------
// mask is int32 (harness widens bool; nonzero == True)
__global__ __launch_bounds__(256,1) void scan_kernel(
    const int* __restrict__ mask,
    const float* __restrict__ fuse_b,
    const float* __restrict__ mln_g,
    const float* __restrict__ mln_b,
    float* __restrict__ out,
    int nblocks)
{
    extern __shared__ float sm[];
    float* cat  = sm;              // [8][2048]: first 1024 = h_t, last 1024 = v_t
    float* auxv = sm + BB*D2;      // 128 floats
    int*   auxi = (int*)(auxv + 128);

    const int tid  = threadIdx.x;
    const int lane = tid & 31;
    const int wib  = tid >> 5;     // 0..7
    const int bid  = blockIdx.x;
    const int gw   = bid*8 + wib;
    const int nw   = nblocks*8;
    const int nA   = nblocks - 8;  // CTAs doing Phase A (blocks 8..nblocks-1)
    // cr = V scale entering step t (includes decay of all steps < t); actual_V = cr*stored_V
    double cr = 1.0;

    for (int t=0; t<TT; t++){
        float crf = (float)cr;
        float invcr = 1.f/crf;

        // ---- stage h_t into smem (q half of cat) ----
        for (int idx=tid; idx < BB*DD/4; idx += 256){
            int b = idx>>8, j4 = idx&255;
            *(float4*)(cat + b*D2 + j4*4) =
                *(const float4*)(g_h + ((size_t)(b*TT+t))*DD + j4*4);
        }
        __syncthreads();

        if (bid < 8){
            // ---- blocks 0-7: ONLY deferred Phase D for step t-1 (no Phase A share) ----
            if (t>0)
                phaseD(bid, t-1, invcr, mln_g, mln_b, out, auxv, tid);
        } else {
            // ---- Phase A on blocks 8..: balanced contiguous row chunks ----
            // lane mapping: 8-lane group g=lane>>3 owns head g; 5-shuffle reduction.
            int active = bid - 8;
            int r0 = (active    * SS) / nA;
            int r1 = ((active+1)* SS) / nA;
            const int hg = lane >> 3, su = lane & 7;
            const int fbase = hg*64 + su;       // float4 index within the 256-float4 row
            for (int s = r0 + wib; s < r1; s += 8){
                const float4* Kr = (const float4*)(g_K + (size_t)s*DD);
                float4 kreg[8];
#pragma unroll
                for (int j=0;j<8;j++) kreg[j] = Kr[fbase + 8*j];
                for (int b=0;b<BB;b++){
                    const float4* qb = (const float4*)(cat + b*D2);
                    float p = 0.f;
#pragma unroll
                    for (int j=0;j<8;j++){
                        float4 q = qb[fbase + 8*j];
                        p += kreg[j].x*q.x + kreg[j].y*q.y + kreg[j].z*q.z + kreg[j].w*q.w;
                    }
                    // head sum within 8-lane group
                    p += __shfl_xor_sync(0xffffffffu, p, 1);
                    p += __shfl_xor_sync(0xffffffffu, p, 2);
                    p += __shfl_xor_sync(0xffffffffu, p, 4);
                    // full-row sum across the 4 groups
                    float tsum = p + __shfl_xor_sync(0xffffffffu, p, 8);
                    tsum += __shfl_xor_sync(0xffffffffu, tsum, 16);
                    if (su == 0){
                        g_scores[(b*HH+hg)*SS + s] = p * 0.0625f;
                        if (hg == 0) g_sw[b*SS + s] = tsum * 0.03125f;
                    }
                }
            }
        }
        gsync(nblocks);   // scores/sw ready AND D(t-1)'s V writes visible

        // ---- Phase B: top-8 + softmax + V gather (32 blocks) || sw reduce (8 blocks) ----
        if (bid < 32){
            int b = bid>>2, h = bid&3;
            const float* sc = g_scores + (b*HH+h)*SS;
            // warp-local top-8: warps 0..7 each own 256 contiguous scores
            {
                float vals[8];
                const int base = wib*256 + lane;
#pragma unroll
                for (int i=0;i<8;i++) vals[i] = sc[base + i*32];
                for (int k=0;k<8;k++){
                    float bv=-1e30f; int bi=0x7fffffff;
#pragma unroll
                    for (int i=0;i<8;i++){
                        int idx = base + i*32;
                        float v = vals[i];
                        if (v>bv || (v==bv && idx<bi)){ bv=v; bi=idx; }
                    }
#pragma unroll
                    for (int o=16;o;o>>=1){
                        float ov=__shfl_xor_sync(0xffffffffu,bv,o);
                        int   oi=__shfl_xor_sync(0xffffffffu,bi,o);
                        if (ov>bv || (ov==bv && oi<bi)){ bv=ov; bi=oi; }
                    }
                    if (lane==k){ auxv[wib*8+k]=bv; auxi[wib*8+k]=bi; }
                    int local = bi - wib*256;
                    if ((local&31)==lane) vals[local>>5] = -1e30f;
                }
            }
            __syncthreads();
            // warp 0 merges 64 candidates -> global top-8, softmax weights
            if (wib==0){
                float c0 = auxv[lane],    c1 = auxv[lane+32];
                int   i0 = auxi[lane],    i1 = auxi[lane+32];
                float topv[8]; int topi[8];
#pragma unroll
                for (int k=0;k<8;k++){
                    float bv; int bi;
                    if (c0>c1 || (c0==c1 && i0<i1)){ bv=c0; bi=i0; } else { bv=c1; bi=i1; }
#pragma unroll
                    for (int o=16;o;o>>=1){
                        float ov=__shfl_xor_sync(0xffffffffu,bv,o);
                        int   oi=__shfl_xor_sync(0xffffffffu,bi,o);
                        if (ov>bv || (ov==bv && oi<bi)){ bv=ov; bi=oi; }
                    }
                    topv[k]=bv; topi[k]=bi;
                    if (i0==bi){ c0=-1e30f; i0=0x7fffffff; }
                    if (i1==bi){ c1=-1e30f; i1=0x7fffffff; }
                }
                float m0 = topv[0], sum=0.f, w8[8];
#pragma unroll
                for (int k=0;k<8;k++){ w8[k]=expf(topv[k]-m0); sum += w8[k]; }
                float inv = 1.f/sum;
                if (lane<8){ auxv[64+lane] = w8[lane]*inv; auxi[64+lane] = topi[lane]; }
            }
            __syncthreads();
            // gather V (all 256 threads; Dh=256)
            {
                float acc = 0.f;
#pragma unroll
                for (int k=0;k<8;k++)
                    acc += auxv[64+k] * g_V[(size_t)auxi[64+k]*DD + h*256 + tid];
                g_vt[b*DD + h*256 + tid] = acc * crf;
            }
        } else if (bid < 40){
            int b = bid - 32;
            const float* sw = g_sw + b*SS;
            float bv=-1e30f; int bi=0x7fffffff;
            for (int s=tid;s<SS;s+=256){
                float v = sw[s];
                if (v>bv || (v==bv && s<bi)){ bv=v; bi=s; }
            }
#pragma unroll
            for (int o=16;o;o>>=1){
                float ov = __shfl_xor_sync(0xffffffffu,bv,o);
                int   oi = __shfl_xor_sync(0xffffffffu,bi,o);
                if (ov>bv || (ov==bv && oi<bi)){ bv=ov; bi=oi; }
            }
            if (lane==0){ auxv[wib]=bv; auxi[wib]=bi; }
            __syncthreads();
            if (tid==0){
                float fv=auxv[0]; int fi=auxi[0];
#pragma unroll
                for (int w=1;w<8;w++){
                    float ov=auxv[w]; int oi=auxi[w];
                    if (ov>fv || (ov==fv && oi<fi)){ fv=ov; fi=oi; }
                }
                auxv[8]=fv; auxi[8]=fi;
            }
            __syncthreads();
            float M = auxv[8];
            float ps=0.f;
            for (int s=tid;s<SS;s+=256) ps += expf(sw[s]-M);
#pragma unroll
            for (int o=16;o;o>>=1) ps += __shfl_xor_sync(0xffffffffu,ps,o);
            if (lane==0) auxv[16+wib]=ps;
            __syncthreads();
            if (tid==0){
                float sum=0.f;
#pragma unroll
                for (int w=0;w<8;w++) sum += auxv[16+w];
                float sur = 1.f - 1.f/sum;
                float gate = (mask[b*TT+t] != 0) ? 1.f : 0.f;
                g_lr[b]  = (sur > 0.6f ? 1.0f : 0.1f) * gate;
                g_slot[b] = auxi[8];
            }
        }
        gsync(nblocks);

        // ---- Phase C: fusion GEMV (1024 col-tasks) + K update + V snapshot ----
        for (int idx=tid; idx < BB*DD/4; idx += 256){
            int b = idx>>8, j4 = idx&255;
            *(float4*)(cat + b*D2 + 1024 + j4*4) = *(const float4*)(g_vt + b*DD + j4*4);
        }
        __syncthreads();
        for (int task=gw; task<1088; task+=nw){
            if (task < 1024){
                int j = task;
                const float4* Wr = (const float4*)(g_fuseWT + (size_t)j*D2);
                float4 wreg[16];
#pragma unroll
                for (int c=0;c<16;c++) wreg[c] = Wr[lane + 32*c];
                float res[BB];
                for (int b=0;b<BB;b++){
                    float acc=0.f;
#pragma unroll
                    for (int c=0;c<16;c++){
                        float4 x = *(const float4*)(cat + b*D2 + 4*(lane + 32*c));
                        acc += wreg[c].x*x.x + wreg[c].y*x.y + wreg[c].z*x.z + wreg[c].w*x.w;
                    }
#pragma unroll
                    for (int o=16;o;o>>=1) acc += __shfl_xor_sync(0xffffffffu,acc,o);
                    res[b]=acc;
                }
                if (lane==0){
                    float fb = fuse_b[j];
#pragma unroll
                    for (int b=0;b<BB;b++)
                        g_fusedpre[b*DD + j] = res[b] + fb + cat[b*D2 + j]; // + h_t residual
                }
            } else if (task < 1056){
                int col = (task-1024)*32 + lane;
                int   sl[BB]; float lrv[BB], oldk[BB];
#pragma unroll
                for (int b=0;b<BB;b++){ sl[b]=g_slot[b]; lrv[b]=g_lr[b]; }
#pragma unroll
                for (int b=0;b<BB;b++) oldk[b] = g_K[(size_t)sl[b]*DD + col];
#pragma unroll
                for (int b=0;b<BB;b++)
                    g_K[(size_t)sl[b]*DD + col] += lrv[b]*(cat[b*D2 + col] - oldk[b]);
            } else {
                int col = (task-1056)*32 + lane;
#pragma unroll
                for (int b=0;b<BB;b++)
                    g_oldV[b*DD + col] = g_V[(size_t)g_slot[b]*DD + col];
            }
        }
        gsync(nblocks);   // fusedpre/oldV/K ready for D(t) and A(t+1)

        // apply this step's decay to the carried scale (precomputed anyt flag)
        if (g_anyt[t]) cr *= 0.9995;
    }

    // final deferred Phase D for t = TT-1
    if (bid < BB){
        float invc = 1.f/(float)cr;
        phaseD(bid, TT-1, invc, mln_g, mln_b, out, auxv, tid);
    }
}

// ---------------- launch ----------------
extern "C" void kernel_launch(void* const* d_in, const int* in_sizes, int n_in,
                              void* d_out, int out_size)
{
    const float* x      = (const float*)d_in[0];
    const int*   mask   = (const int*)d_in[1];     // bool widened to int32 by harness
    const float* W1     = (const float*)d_in[2];
    const float* b1     = (const float*)d_in[3];
    const float* W2     = (const float*)d_in[4];
    const float* b2     = (const float*)d_in[5];
    const float* ln_g   = (const float*)d_in[6];
    const float* ln_b   = (const float*)d_in[7];
    const float* fuse_W = (const float*)d_in[8];
    const float* fuse_b = (const float*)d_in[9];
    const float* mln_g  = (const float*)d_in[10];
    const float* mln_b  = (const float*)d_in[11];
    const float* mem_K  = (const float*)d_in[12];
    const float* mem_V  = (const float*)d_in[13];
    float* out = (float*)d_out;

    void *p_h, *p_tmp, *p_y, *p_K, *p_V;
    cudaGetSymbolAddress(&p_h,   g_h);
    cudaGetSymbolAddress(&p_tmp, g_tmp);
    cudaGetSymbolAddress(&p_y,   g_y);
    cudaGetSymbolAddress(&p_K,   g_K);
    cudaGetSymbolAddress(&p_V,   g_V);

    cudaMemcpyAsync(p_h, x,     (size_t)BB*TT*DD*sizeof(float), cudaMemcpyDeviceToDevice, 0);
    cudaMemcpyAsync(p_K, mem_K, (size_t)SS*DD*sizeof(float),    cudaMemcpyDeviceToDevice, 0);
    cudaMemcpyAsync(p_V, mem_V, (size_t)SS*DD*sizeof(float),    cudaMemcpyDeviceToDevice, 0);

    init_kernel<<<dim3(DD/32, D2/32), dim3(32,8), 0, 0>>>(fuse_W, mask);

    for (int i=0;i<2;i++){
        gemm128<<<dim3(D2/128, (BB*TT)/128), 256, 0, 0>>>(
            (const float*)p_h, W1 + (size_t)i*DD*D2, b1 + (size_t)i*D2,
            (float*)p_tmp, BB*TT, D2, DD, 1);
        gemm128<<<dim3(DD/128, (BB*TT)/128), 256, 0, 0>>>(
            (const float*)p_tmp, W2 + (size_t)i*D2*DD, b2 + (size_t)i*DD,
            (float*)p_y, BB*TT, DD, D2, 0);
        ln_res<<<BB*TT, 256, 0, 0>>>((float*)p_h, (const float*)p_y,
                                     ln_g + (size_t)i*DD, ln_b + (size_t)i*DD);
    }

    int nsm = 148;
    cudaDeviceGetAttribute(&nsm, cudaDevAttrMultiProcessorCount, 0);
    size_t smem = 120*1024;  // forces 1 CTA/SM -> all CTAs co-resident for the grid barrier
    cudaFuncSetAttribute(scan_kernel, cudaFuncAttributeMaxDynamicSharedMemorySize, (int)smem);
    scan_kernel<<<nsm, 256, smem, 0>>>(mask, fuse_b, mln_g, mln_b, out, nsm);
}